// round 16
// baseline (speedup 1.0000x reference)
#include <cuda_runtime.h>
#include <cuda_fp16.h>
#include <cstdint>

#define N_TOTAL 16384
#define C_DIM   128
#define K_CODES 8192
#define HW      1024

// ---------------- device scratch ----------------
__device__ float g_sumw2[K_CODES];
__device__ float g_sumx2[N_TOTAL];
__device__ float g_counts[K_CODES];
__device__ float g_sums[K_CODES * C_DIM];
__device__ unsigned long long g_best[N_TOTAL];
__device__ __half g_wsp[2][K_CODES * C_DIM];   // w*1024 split: h, m
__device__ __half g_xsp[2][N_TOTAL * C_DIM];   // x split: h, m

// ---------------- helpers ----------------
__device__ __forceinline__ uint32_t smem_u32(const void* p) {
    uint32_t a;
    asm("{ .reg .u64 t; cvta.to.shared.u64 t, %1; cvt.u32.u64 %0, t; }" : "=r"(a) : "l"(p));
    return a;
}
__device__ __forceinline__ void cp16(uint32_t s, const void* g) {
    asm volatile("cp.async.cg.shared.global [%0], [%1], 16;" :: "r"(s), "l"(g) : "memory");
}
#define CP_COMMIT() asm volatile("cp.async.commit_group;" ::: "memory")
#define SWZ(b) ((b) ^ (((b) >> 3) & 0x70))

#define LDSM4(r, a) \
    asm volatile("ldmatrix.sync.aligned.m8n8.x4.shared.b16 {%0,%1,%2,%3}, [%4];" \
        : "=r"((r)[0]), "=r"((r)[1]), "=r"((r)[2]), "=r"((r)[3]) : "r"(a))

#define MMA(c, a, b0v, b1v) \
    asm volatile("mma.sync.aligned.m16n8k16.row.col.f32.f16.f16.f32 " \
        "{%0,%1,%2,%3},{%4,%5,%6,%7},{%8,%9},{%0,%1,%2,%3};" \
        : "+f"((c)[0]), "+f"((c)[1]), "+f"((c)[2]), "+f"((c)[3]) \
        : "r"((a)[0]), "r"((a)[1]), "r"((a)[2]), "r"((a)[3]), "r"(b0v), "r"(b1v))

// ---------------- K1: fused prep ----------------
// blocks 0..1023:   split w*1024 into fp16 limbs (float4/uint2), ||w||^2,
//                   zero sums/counts/best
// blocks 1024..1279: transpose x (65-stride pad, conflict-free), split, ||x||^2
__global__ void prep_kernel(const float* __restrict__ w,
                            const float* __restrict__ enc) {
    __shared__ float sm[128 * 65];
    int t = threadIdx.x;
    if (blockIdx.x < 1024) {
        int idx4 = blockIdx.x * 256 + t;   // one float4 per thread
        float4 wv = ((const float4*)w)[idx4];
        float v0 = wv.x * 1024.0f, v1 = wv.y * 1024.0f;
        float v2 = wv.z * 1024.0f, v3 = wv.w * 1024.0f;
        __half h0 = __float2half_rn(v0), h1 = __float2half_rn(v1);
        __half h2 = __float2half_rn(v2), h3 = __float2half_rn(v3);
        __half m0 = __float2half_rn(v0 - __half2float(h0));
        __half m1 = __float2half_rn(v1 - __half2float(h1));
        __half m2 = __float2half_rn(v2 - __half2float(h2));
        __half m3 = __float2half_rn(v3 - __half2float(h3));
        __half2 ph0 = __halves2half2(h0, h1), ph1 = __halves2half2(h2, h3);
        __half2 pm0 = __halves2half2(m0, m1), pm1 = __halves2half2(m2, m3);
        uint2 uh = make_uint2(*(uint32_t*)&ph0, *(uint32_t*)&ph1);
        uint2 um = make_uint2(*(uint32_t*)&pm0, *(uint32_t*)&pm1);
        ((uint2*)g_wsp[0])[idx4] = uh;
        ((uint2*)g_wsp[1])[idx4] = um;
        ((float4*)g_sums)[idx4] = make_float4(0.f, 0.f, 0.f, 0.f);
        // ||w||^2: identical summation order to all prior rounds
        int k = blockIdx.x * 8 + (t >> 5);
        int lane = t & 31;
        const float* row = w + k * C_DIM;
        float s = 0.f;
#pragma unroll
        for (int j = 0; j < 4; j++) { float v = row[lane + j * 32]; s = fmaf(v, v, s); }
#pragma unroll
        for (int off = 16; off; off >>= 1) s += __shfl_xor_sync(0xffffffffu, s, off);
        if (lane == 0) g_sumw2[k] = s;
        if (blockIdx.x < 32) g_counts[blockIdx.x * 256 + t] = 0.f;
        if (blockIdx.x < 64) g_best[blockIdx.x * 256 + t] = ~0ull;
        return;
    }
    int n0 = (blockIdx.x - 1024) * 64;
    const float* xb = enc + (n0 >> 10) * (C_DIM * HW) + (n0 & (HW - 1));
#pragma unroll
    for (int i = 0; i < 32; i++) {
        int lin = i * 256 + t, c = lin >> 6, nl = lin & 63;
        sm[c * 65 + nl] = xb[c * HW + nl];   // banks (c+nl)%32: conflict-free
    }
    __syncthreads();
    // writeout: 4 consecutive c per thread -> 8B uint2 stores (256B/warp)
#pragma unroll
    for (int i = 0; i < 8; i++) {
        int unit = i * 256 + t;
        int n = unit >> 5, c4 = (unit & 31) * 4;
        __half hh[4], mm[4];
#pragma unroll
        for (int j = 0; j < 4; j++) {
            float v = sm[(c4 + j) * 65 + n];
            hh[j] = __float2half_rn(v);
            mm[j] = __float2half_rn(v - __half2float(hh[j]));
        }
        __half2 ph0 = __halves2half2(hh[0], hh[1]), ph1 = __halves2half2(hh[2], hh[3]);
        __half2 pm0 = __halves2half2(mm[0], mm[1]), pm1 = __halves2half2(mm[2], mm[3]);
        uint2 uh = make_uint2(*(uint32_t*)&ph0, *(uint32_t*)&ph1);
        uint2 um = make_uint2(*(uint32_t*)&pm0, *(uint32_t*)&pm1);
        size_t off = (size_t)(n0 + n) * C_DIM + c4;
        *(uint2*)(g_xsp[0] + off) = uh;
        *(uint2*)(g_xsp[1] + off) = um;
    }
    if (t < 64) {
        float s = 0.f;
        for (int c = 0; c < 128; c++) { float v = sm[c * 65 + t]; s = fmaf(v, v, s); }
        g_sumx2[n0 + t] = s;
    }
}

// ---------------- K2: tensor GEMM dist + argmin ----------------
// CTA tile 128(M) x 128(N), 8 warps (4x2 grid, warp tile 32x64), 2 CTAs/SM.
// 3 limb products (hh, hm, mh) x K=128 -> 6 chunks of K=64.
// 3-stage cp.async pipeline, one sync per chunk; prefetch issued AFTER the
// first fragment loads so the tensor pipe restarts immediately post-barrier.
#define STAGES      3
#define STAGE_BYTES 32768          // A 16KB + B 16KB
#define OFF_SW2     98304
#define OFF_SX2     98816
#define DSMEM_BYTES 99328

__global__ void __launch_bounds__(256, 2)
dist_kernel() {
    extern __shared__ char sm[];
    const uint32_t sb = smem_u32(sm);
    const int t = threadIdx.x, l = t & 31, wi = t >> 5;
    const int wm = wi >> 1, wn = wi & 1;          // 4 x 2 warp grid
    const int m0 = blockIdx.y * 128, n0 = blockIdx.x * 128;

    float* sw2s = (float*)(sm + OFF_SW2);
    float* sx2s = (float*)(sm + OFF_SX2);
    if (t < 128) sw2s[t] = g_sumw2[n0 + t];
    else         sx2s[t - 128] = g_sumx2[m0 + t - 128];

    auto issue = [&](int cc) {
        int st = cc % STAGES;
        int pr = cc >> 1, koff = (cc & 1) * 64;
        int sa = (pr == 2) ? 1 : 0;   // A limb: h,h,m
        int sbl = (pr == 1) ? 1 : 0;  // B limb: h,m,h
        const __half* ga = &g_xsp[sa][(size_t)m0 * 128 + koff];
        const __half* gb = &g_wsp[sbl][(size_t)n0 * 128 + koff];
        uint32_t abase = sb + st * STAGE_BYTES;
        uint32_t bbase = abase + 16384;
#pragma unroll
        for (int u = t; u < 1024; u += 256) {
            int r = u >> 3, c16 = u & 7;
            cp16(abase + SWZ(r * 128 + c16 * 16), ga + r * 128 + c16 * 8);
        }
#pragma unroll
        for (int u = t; u < 1024; u += 256) {
            int r = u >> 3, c16 = u & 7;
            cp16(bbase + SWZ(r * 128 + c16 * 16), gb + r * 128 + c16 * 8);
        }
    };

    float acc[2][8][4];
#pragma unroll
    for (int mi = 0; mi < 2; mi++)
#pragma unroll
        for (int ni = 0; ni < 8; ni++)
#pragma unroll
            for (int c = 0; c < 4; c++) acc[mi][ni][c] = 0.f;

    issue(0); CP_COMMIT();
    issue(1); CP_COMMIT();

    for (int cc = 0; cc < 6; cc++) {
        const int st = cc % STAGES;
        asm volatile("cp.async.wait_group 1;" ::: "memory");
        __syncthreads();

        const uint32_t abase = sb + st * STAGE_BYTES;
        const uint32_t bbase = abase + 16384;

        auto load_frags = [&](int ks, uint32_t a[2][4], uint32_t b[4][4]) {
#pragma unroll
            for (int mi = 0; mi < 2; mi++) {
                int row = wm * 32 + mi * 16 + (l & 15);
                LDSM4(a[mi], abase + SWZ(row * 128 + ks * 32 + ((l >> 4) * 16)));
            }
#pragma unroll
            for (int ni2 = 0; ni2 < 4; ni2++) {
                int row = wn * 64 + ni2 * 16 + ((l >> 4) << 3) + (l & 7);
                LDSM4(b[ni2], bbase + SWZ(row * 128 + ks * 32 + (((l >> 3) & 1) * 16)));
            }
        };

        // ks=0 fragment loads FIRST: tensor pipe restarts right after the sync;
        // the prefetch for chunk cc+2 issues in the MMA shadow. WAR-safe: its
        // buffer (cc+2)%3 was last read by chunk cc-1, done before this sync.
        uint32_t a0[2][4], b0[4][4];
        load_frags(0, a0, b0);
        if (cc + 2 < 6) issue(cc + 2);
        CP_COMMIT();   // uniform commit keeps wait_group counting exact
#pragma unroll
        for (int mi = 0; mi < 2; mi++)
#pragma unroll
            for (int ni = 0; ni < 8; ni++)
                MMA(acc[mi][ni], a0[mi], b0[ni >> 1][(ni & 1) * 2], b0[ni >> 1][(ni & 1) * 2 + 1]);

#pragma unroll
        for (int ks = 1; ks < 4; ks++) {
            uint32_t a[2][4], b[4][4];
            load_frags(ks, a, b);
#pragma unroll
            for (int mi = 0; mi < 2; mi++)
#pragma unroll
                for (int ni = 0; ni < 8; ni++)
                    MMA(acc[mi][ni], a[mi], b[ni >> 1][(ni & 1) * 2], b[ni >> 1][(ni & 1) * 2 + 1]);
        }
    }

    // Epilogue: acc = 1024*dot; acc/512 = 2*dot (exact scale).
    // dist = round32(sx2 + sw2) - round32(2*dot); lexicographic (dist, idx) min.
#pragma unroll
    for (int mi = 0; mi < 2; mi++) {
#pragma unroll
        for (int half = 0; half < 2; half++) {
            int rl = wm * 32 + mi * 16 + (l >> 2) + half * 8;
            float sx = sx2s[rl];
            unsigned long long key = ~0ull;
#pragma unroll
            for (int ni = 0; ni < 8; ni++) {
#pragma unroll
                for (int c = 0; c < 2; c++) {
                    int col = wn * 64 + ni * 8 + (l & 3) * 2 + c;
                    float two_dot = __fmul_rn(acc[mi][ni][half * 2 + c], 1.0f / 512.0f);
                    float d = __fsub_rn(__fadd_rn(sx, sw2s[col]), two_dot);
                    unsigned long long k =
                        ((unsigned long long)__float_as_uint(d) << 32) | (unsigned)(n0 + col);
                    key = (k < key) ? k : key;
                }
            }
            unsigned long long o1 = __shfl_xor_sync(0xffffffffu, key, 1);
            key = (o1 < key) ? o1 : key;
            unsigned long long o2 = __shfl_xor_sync(0xffffffffu, key, 2);
            key = (o2 < key) ? o2 : key;
            if ((l & 3) == 0) atomicMin(&g_best[m0 + rl], key);
        }
    }
}

// ---------------- K3: finalize ids + scatter counts/sums + q output ---------
// 128 blocks x 512 threads: thread = (hw 0..127, cgroup 0..3), 32 c-iters.
// w gathered as float4 (one 16B load per 4 channels).
__global__ void __launch_bounds__(512)
scatter_kernel(const float* __restrict__ enc, const float* __restrict__ w,
               float* __restrict__ out_ids, float* __restrict__ outq) {
    __shared__ int ids_s[128];
    int n0 = blockIdx.x * 128;
    int t = threadIdx.x;
    if (t < 128) {
        int id = (int)(g_best[n0 + t] & 0xFFFFFFFFull);
        out_ids[n0 + t] = (float)id;
        ids_s[t] = id;
        atomicAdd(&g_counts[id], 1.0f);
    }
    __syncthreads();
    int hw = t & 127, cg = t >> 7;
    int b = n0 >> 10, hw0 = n0 & (HW - 1);
    const float* xb = enc + b * (C_DIM * HW) + hw0;
    float* qb = outq + b * (C_DIM * HW) + hw0;
    int id = ids_s[hw];
#pragma unroll 2
    for (int j4 = 0; j4 < 8; j4++) {
        int c = cg * 32 + j4 * 4;
        float4 wv = *(const float4*)(w + id * C_DIM + c);
        float q[4] = {wv.x, wv.y, wv.z, wv.w};
#pragma unroll
        for (int j = 0; j < 4; j++) {
            float v = xb[(c + j) * HW + hw];
            atomicAdd(&g_sums[id * C_DIM + c + j], v);
            qb[(c + j) * HW + hw] = q[j];
        }
    }
}

// ---------------- K4: EMA update (vectorized float4) ----------------
__global__ void neww_kernel(const float* __restrict__ w, float* __restrict__ outw) {
    int idx4 = blockIdx.x * 256 + threadIdx.x;   // 0..262143
    int k = idx4 >> 5;                           // 32 float4 per code row
    float cnt = g_counts[k] + 1e-12f;
    float4 s  = ((const float4*)g_sums)[idx4];
    float4 wv = *(const float4*)(w + idx4 * 4);
    float4 o;
    o.x = 0.99f * wv.x + 0.01f * (s.x / cnt);
    o.y = 0.99f * wv.y + 0.01f * (s.y / cnt);
    o.z = 0.99f * wv.z + 0.01f * (s.z / cnt);
    o.w = 0.99f * wv.w + 0.01f * (s.w / cnt);
    *(float4*)(outw + idx4 * 4) = o;
}

// ---------------------------------------------------------------------------
extern "C" void kernel_launch(void* const* d_in, const int* in_sizes, int n_in,
                              void* d_out, int out_size) {
    const float* enc = (const float*)d_in[0];
    const float* w   = (const float*)d_in[1];
    float* out     = (float*)d_out;
    float* out_ids = out;
    float* out_q   = out + N_TOTAL;
    float* out_w   = out + N_TOTAL + N_TOTAL * C_DIM;

    cudaFuncSetAttribute(dist_kernel,
                         cudaFuncAttributeMaxDynamicSharedMemorySize, DSMEM_BYTES);

    prep_kernel<<<1024 + N_TOTAL / 64, 256>>>(w, enc);
    dist_kernel<<<dim3(K_CODES / 128, N_TOTAL / 128), 256, DSMEM_BYTES>>>();
    scatter_kernel<<<N_TOTAL / 128, 512>>>(enc, w, out_ids, out_q);
    neww_kernel<<<(K_CODES * C_DIM) / 1024, 256>>>(w, out_w);
}

// round 17
// speedup vs baseline: 1.0467x; 1.0467x over previous
#include <cuda_runtime.h>
#include <cuda_fp16.h>
#include <cstdint>

#define N_TOTAL 16384
#define C_DIM   128
#define K_CODES 8192
#define HW      1024

// ---------------- device scratch ----------------
__device__ float g_sumw2[K_CODES];
__device__ float g_sumx2[N_TOTAL];
__device__ float g_counts[K_CODES];
__device__ float g_sums[K_CODES * C_DIM];
__device__ unsigned long long g_best[N_TOTAL];
__device__ __half g_wsp[2][K_CODES * C_DIM];   // w*1024 split: h, m
__device__ __half g_xsp[2][N_TOTAL * C_DIM];   // x split: h, m

// ---------------- helpers ----------------
__device__ __forceinline__ uint32_t smem_u32(const void* p) {
    uint32_t a;
    asm("{ .reg .u64 t; cvta.to.shared.u64 t, %1; cvt.u32.u64 %0, t; }" : "=r"(a) : "l"(p));
    return a;
}
__device__ __forceinline__ void cp16(uint32_t s, const void* g) {
    asm volatile("cp.async.cg.shared.global [%0], [%1], 16;" :: "r"(s), "l"(g) : "memory");
}
#define CP_COMMIT() asm volatile("cp.async.commit_group;" ::: "memory")
#define SWZ(b) ((b) ^ (((b) >> 3) & 0x70))

#define LDSM4(r, a) \
    asm volatile("ldmatrix.sync.aligned.m8n8.x4.shared.b16 {%0,%1,%2,%3}, [%4];" \
        : "=r"((r)[0]), "=r"((r)[1]), "=r"((r)[2]), "=r"((r)[3]) : "r"(a))

#define MMA(c, a, b0v, b1v) \
    asm volatile("mma.sync.aligned.m16n8k16.row.col.f32.f16.f16.f32 " \
        "{%0,%1,%2,%3},{%4,%5,%6,%7},{%8,%9},{%0,%1,%2,%3};" \
        : "+f"((c)[0]), "+f"((c)[1]), "+f"((c)[2]), "+f"((c)[3]) \
        : "r"((a)[0]), "r"((a)[1]), "r"((a)[2]), "r"((a)[3]), "r"(b0v), "r"(b1v))

// ---------------- K1: fused prep ----------------
// blocks 0..1023:   split w*1024 into fp16 limbs (float4/uint2), ||w||^2,
//                   zero sums/counts/best
// blocks 1024..1279: transpose x (65-stride pad, conflict-free), split, ||x||^2
__global__ void prep_kernel(const float* __restrict__ w,
                            const float* __restrict__ enc) {
    __shared__ float sm[128 * 65];
    int t = threadIdx.x;
    if (blockIdx.x < 1024) {
        int idx4 = blockIdx.x * 256 + t;   // one float4 per thread
        float4 wv = ((const float4*)w)[idx4];
        float v0 = wv.x * 1024.0f, v1 = wv.y * 1024.0f;
        float v2 = wv.z * 1024.0f, v3 = wv.w * 1024.0f;
        __half h0 = __float2half_rn(v0), h1 = __float2half_rn(v1);
        __half h2 = __float2half_rn(v2), h3 = __float2half_rn(v3);
        __half m0 = __float2half_rn(v0 - __half2float(h0));
        __half m1 = __float2half_rn(v1 - __half2float(h1));
        __half m2 = __float2half_rn(v2 - __half2float(h2));
        __half m3 = __float2half_rn(v3 - __half2float(h3));
        __half2 ph0 = __halves2half2(h0, h1), ph1 = __halves2half2(h2, h3);
        __half2 pm0 = __halves2half2(m0, m1), pm1 = __halves2half2(m2, m3);
        uint2 uh = make_uint2(*(uint32_t*)&ph0, *(uint32_t*)&ph1);
        uint2 um = make_uint2(*(uint32_t*)&pm0, *(uint32_t*)&pm1);
        ((uint2*)g_wsp[0])[idx4] = uh;
        ((uint2*)g_wsp[1])[idx4] = um;
        ((float4*)g_sums)[idx4] = make_float4(0.f, 0.f, 0.f, 0.f);
        // ||w||^2: identical summation order to all prior rounds
        int k = blockIdx.x * 8 + (t >> 5);
        int lane = t & 31;
        const float* row = w + k * C_DIM;
        float s = 0.f;
#pragma unroll
        for (int j = 0; j < 4; j++) { float v = row[lane + j * 32]; s = fmaf(v, v, s); }
#pragma unroll
        for (int off = 16; off; off >>= 1) s += __shfl_xor_sync(0xffffffffu, s, off);
        if (lane == 0) g_sumw2[k] = s;
        if (blockIdx.x < 32) g_counts[blockIdx.x * 256 + t] = 0.f;
        if (blockIdx.x < 64) g_best[blockIdx.x * 256 + t] = ~0ull;
        return;
    }
    int n0 = (blockIdx.x - 1024) * 64;
    const float* xb = enc + (n0 >> 10) * (C_DIM * HW) + (n0 & (HW - 1));
#pragma unroll
    for (int i = 0; i < 32; i++) {
        int lin = i * 256 + t, c = lin >> 6, nl = lin & 63;
        sm[c * 65 + nl] = xb[c * HW + nl];   // banks (c+nl)%32: conflict-free
    }
    __syncthreads();
    // writeout: 4 consecutive c per thread -> 8B uint2 stores (256B/warp)
#pragma unroll
    for (int i = 0; i < 8; i++) {
        int unit = i * 256 + t;
        int n = unit >> 5, c4 = (unit & 31) * 4;
        __half hh[4], mm[4];
#pragma unroll
        for (int j = 0; j < 4; j++) {
            float v = sm[(c4 + j) * 65 + n];
            hh[j] = __float2half_rn(v);
            mm[j] = __float2half_rn(v - __half2float(hh[j]));
        }
        __half2 ph0 = __halves2half2(hh[0], hh[1]), ph1 = __halves2half2(hh[2], hh[3]);
        __half2 pm0 = __halves2half2(mm[0], mm[1]), pm1 = __halves2half2(mm[2], mm[3]);
        uint2 uh = make_uint2(*(uint32_t*)&ph0, *(uint32_t*)&ph1);
        uint2 um = make_uint2(*(uint32_t*)&pm0, *(uint32_t*)&pm1);
        size_t off = (size_t)(n0 + n) * C_DIM + c4;
        *(uint2*)(g_xsp[0] + off) = uh;
        *(uint2*)(g_xsp[1] + off) = um;
    }
    if (t < 64) {
        float s = 0.f;
        for (int c = 0; c < 128; c++) { float v = sm[c * 65 + t]; s = fmaf(v, v, s); }
        g_sumx2[n0 + t] = s;
    }
}

// ---------------- K2: tensor GEMM dist + argmin (R10/R15 config, verbatim) --
// CTA tile 128(M) x 128(N), 8 warps (4x2 grid, warp tile 32x64), 2 CTAs/SM.
// 3 limb products (hh, hm, mh) x K=128 -> 6 chunks of K=64.
// 3-stage cp.async pipeline, one sync per chunk.
#define STAGES      3
#define STAGE_BYTES 32768          // A 16KB + B 16KB
#define OFF_SW2     98304
#define OFF_SX2     98816
#define DSMEM_BYTES 99328

__global__ void __launch_bounds__(256, 2)
dist_kernel() {
    extern __shared__ char sm[];
    const uint32_t sb = smem_u32(sm);
    const int t = threadIdx.x, l = t & 31, wi = t >> 5;
    const int wm = wi >> 1, wn = wi & 1;          // 4 x 2 warp grid
    const int m0 = blockIdx.y * 128, n0 = blockIdx.x * 128;

    float* sw2s = (float*)(sm + OFF_SW2);
    float* sx2s = (float*)(sm + OFF_SX2);
    if (t < 128) sw2s[t] = g_sumw2[n0 + t];
    else         sx2s[t - 128] = g_sumx2[m0 + t - 128];

    auto issue = [&](int cc) {
        int st = cc % STAGES;
        int pr = cc >> 1, koff = (cc & 1) * 64;
        int sa = (pr == 2) ? 1 : 0;   // A limb: h,h,m
        int sbl = (pr == 1) ? 1 : 0;  // B limb: h,m,h
        const __half* ga = &g_xsp[sa][(size_t)m0 * 128 + koff];
        const __half* gb = &g_wsp[sbl][(size_t)n0 * 128 + koff];
        uint32_t abase = sb + st * STAGE_BYTES;
        uint32_t bbase = abase + 16384;
#pragma unroll
        for (int u = t; u < 1024; u += 256) {
            int r = u >> 3, c16 = u & 7;
            cp16(abase + SWZ(r * 128 + c16 * 16), ga + r * 128 + c16 * 8);
        }
#pragma unroll
        for (int u = t; u < 1024; u += 256) {
            int r = u >> 3, c16 = u & 7;
            cp16(bbase + SWZ(r * 128 + c16 * 16), gb + r * 128 + c16 * 8);
        }
    };

    float acc[2][8][4];
#pragma unroll
    for (int mi = 0; mi < 2; mi++)
#pragma unroll
        for (int ni = 0; ni < 8; ni++)
#pragma unroll
            for (int c = 0; c < 4; c++) acc[mi][ni][c] = 0.f;

    issue(0); CP_COMMIT();
    issue(1); CP_COMMIT();

    for (int cc = 0; cc < 6; cc++) {
        const int st = cc % STAGES;
        asm volatile("cp.async.wait_group 1;" ::: "memory");
        __syncthreads();
        if (cc + 2 < 6) issue(cc + 2);
        CP_COMMIT();

        const uint32_t abase = sb + st * STAGE_BYTES;
        const uint32_t bbase = abase + 16384;
#pragma unroll
        for (int ks = 0; ks < 4; ks++) {
            uint32_t a[2][4], b[4][4];
#pragma unroll
            for (int mi = 0; mi < 2; mi++) {
                int row = wm * 32 + mi * 16 + (l & 15);
                LDSM4(a[mi], abase + SWZ(row * 128 + ks * 32 + ((l >> 4) * 16)));
            }
#pragma unroll
            for (int ni2 = 0; ni2 < 4; ni2++) {
                int row = wn * 64 + ni2 * 16 + ((l >> 4) << 3) + (l & 7);
                LDSM4(b[ni2], bbase + SWZ(row * 128 + ks * 32 + (((l >> 3) & 1) * 16)));
            }
#pragma unroll
            for (int mi = 0; mi < 2; mi++)
#pragma unroll
                for (int ni = 0; ni < 8; ni++)
                    MMA(acc[mi][ni], a[mi], b[ni >> 1][(ni & 1) * 2], b[ni >> 1][(ni & 1) * 2 + 1]);
        }
    }

    // Epilogue: acc = 1024*dot; acc/512 = 2*dot (exact scale).
    // dist = round32(sx2 + sw2) - round32(2*dot); lexicographic (dist, idx) min.
#pragma unroll
    for (int mi = 0; mi < 2; mi++) {
#pragma unroll
        for (int half = 0; half < 2; half++) {
            int rl = wm * 32 + mi * 16 + (l >> 2) + half * 8;
            float sx = sx2s[rl];
            unsigned long long key = ~0ull;
#pragma unroll
            for (int ni = 0; ni < 8; ni++) {
#pragma unroll
                for (int c = 0; c < 2; c++) {
                    int col = wn * 64 + ni * 8 + (l & 3) * 2 + c;
                    float two_dot = __fmul_rn(acc[mi][ni][half * 2 + c], 1.0f / 512.0f);
                    float d = __fsub_rn(__fadd_rn(sx, sw2s[col]), two_dot);
                    unsigned long long k =
                        ((unsigned long long)__float_as_uint(d) << 32) | (unsigned)(n0 + col);
                    key = (k < key) ? k : key;
                }
            }
            unsigned long long o1 = __shfl_xor_sync(0xffffffffu, key, 1);
            key = (o1 < key) ? o1 : key;
            unsigned long long o2 = __shfl_xor_sync(0xffffffffu, key, 2);
            key = (o2 < key) ? o2 : key;
            if ((l & 3) == 0) atomicMin(&g_best[m0 + rl], key);
        }
    }
}

// ---------------- K3: finalize ids + scatter counts/sums + q output ---------
// 128 blocks x 512 threads: thread = (hw 0..127, cgroup 0..3), 32 c-iters.
// w gathered as float4 (one 16B load per 4 channels).
__global__ void __launch_bounds__(512)
scatter_kernel(const float* __restrict__ enc, const float* __restrict__ w,
               float* __restrict__ out_ids, float* __restrict__ outq) {
    __shared__ int ids_s[128];
    int n0 = blockIdx.x * 128;
    int t = threadIdx.x;
    if (t < 128) {
        int id = (int)(g_best[n0 + t] & 0xFFFFFFFFull);
        out_ids[n0 + t] = (float)id;
        ids_s[t] = id;
        atomicAdd(&g_counts[id], 1.0f);
    }
    __syncthreads();
    int hw = t & 127, cg = t >> 7;
    int b = n0 >> 10, hw0 = n0 & (HW - 1);
    const float* xb = enc + b * (C_DIM * HW) + hw0;
    float* qb = outq + b * (C_DIM * HW) + hw0;
    int id = ids_s[hw];
#pragma unroll 2
    for (int j4 = 0; j4 < 8; j4++) {
        int c = cg * 32 + j4 * 4;
        float4 wv = *(const float4*)(w + id * C_DIM + c);
        float q[4] = {wv.x, wv.y, wv.z, wv.w};
#pragma unroll
        for (int j = 0; j < 4; j++) {
            float v = xb[(c + j) * HW + hw];
            atomicAdd(&g_sums[id * C_DIM + c + j], v);
            qb[(c + j) * HW + hw] = q[j];
        }
    }
}

// ---------------- K4: EMA update (vectorized float4) ----------------
__global__ void neww_kernel(const float* __restrict__ w, float* __restrict__ outw) {
    int idx4 = blockIdx.x * 256 + threadIdx.x;   // 0..262143
    int k = idx4 >> 5;                           // 32 float4 per code row
    float cnt = g_counts[k] + 1e-12f;
    float4 s  = ((const float4*)g_sums)[idx4];
    float4 wv = *(const float4*)(w + idx4 * 4);
    float4 o;
    o.x = 0.99f * wv.x + 0.01f * (s.x / cnt);
    o.y = 0.99f * wv.y + 0.01f * (s.y / cnt);
    o.z = 0.99f * wv.z + 0.01f * (s.z / cnt);
    o.w = 0.99f * wv.w + 0.01f * (s.w / cnt);
    *(float4*)(outw + idx4 * 4) = o;
}

// ---------------------------------------------------------------------------
extern "C" void kernel_launch(void* const* d_in, const int* in_sizes, int n_in,
                              void* d_out, int out_size) {
    const float* enc = (const float*)d_in[0];
    const float* w   = (const float*)d_in[1];
    float* out     = (float*)d_out;
    float* out_ids = out;
    float* out_q   = out + N_TOTAL;
    float* out_w   = out + N_TOTAL + N_TOTAL * C_DIM;

    cudaFuncSetAttribute(dist_kernel,
                         cudaFuncAttributeMaxDynamicSharedMemorySize, DSMEM_BYTES);

    prep_kernel<<<1024 + N_TOTAL / 64, 256>>>(w, enc);
    dist_kernel<<<dim3(K_CODES / 128, N_TOTAL / 128), 256, DSMEM_BYTES>>>();
    scatter_kernel<<<N_TOTAL / 128, 512>>>(enc, w, out_ids, out_q);
    neww_kernel<<<(K_CODES * C_DIM) / 1024, 256>>>(w, out_w);
}